// round 3
// baseline (speedup 1.0000x reference)
#include <cuda_runtime.h>
#include <cstdint>

#define C1 64
#define C2 128
#define C3 256
#define DD 128
#define TM 128

// ---------------- static device scratch (no allocs allowed) ----------------
__device__ float g_y2[(size_t)131072 * DD];        // level-2 merged features
__device__ int   g_perm1[420000 + 4096];
__device__ int   g_perm2[131072 + 4096];
__device__ float g_B3[8 * 12 * 4096];              // [bin][chunk][frag-layout 16KB tile]
__device__ float g_B2[8 * 6 * 4096];
__device__ int   g_cnt1[8], g_cnt2[8];
__device__ int   g_st1[9], g_st2[9];
__device__ int   g_cur1[8], g_cur2[8];

// ---------------- helpers ----------------
__device__ __forceinline__ float tfr(float x) {
    uint32_t u;
    asm("cvt.rna.tf32.f32 %0, %1;" : "=r"(u) : "f"(x));
    return __uint_as_float(u);
}
__device__ __forceinline__ uint32_t smem_u32(const void* p) {
    uint32_t a;
    asm("{ .reg .u64 t; cvta.to.shared.u64 t, %1; cvt.u32.u64 %0, t; }" : "=r"(a) : "l"(p));
    return a;
}
__device__ __forceinline__ void cp16(float* dst_smem, const float* src) {
    uint32_t d = smem_u32(dst_smem);
    asm volatile("cp.async.ca.shared.global [%0], [%1], 16;" :: "r"(d), "l"(src) : "memory");
}
__device__ __forceinline__ void cp_commit() {
    asm volatile("cp.async.commit_group;" ::: "memory");
}
__device__ __forceinline__ void cp_wait1() {
    asm volatile("cp.async.wait_group 1;" ::: "memory");
}
__device__ __forceinline__ void mma_tf32(float* c, const uint32_t* a, const uint32_t* b) {
    asm volatile(
        "mma.sync.aligned.m16n8k8.row.col.f32.tf32.tf32.f32 "
        "{%0,%1,%2,%3}, {%4,%5,%6,%7}, {%8,%9}, {%0,%1,%2,%3};\n"
        : "+f"(c[0]), "+f"(c[1]), "+f"(c[2]), "+f"(c[3])
        : "r"(a[0]), "r"(a[1]), "r"(a[2]), "r"(a[3]), "r"(b[0]), "r"(b[1]));
}

// Fragment-layout address within a 128x32 chunk tile (float index):
//   value M[row][kc] lives at  row*32 + ((((kc&3)*2 + (kc>>4...)) ) ...)
//   slot = (kc&3)*8 + (kc>>2);  block = slot>>2;  w = slot&3;
//   phys = row*32 + ((block ^ (row&7)) << 2) + w
__device__ __forceinline__ int frag_addr(int row, int kc) {
    int tg = kc & 3, j = kc >> 2;
    int block = tg * 2 + (j >> 2);
    int w = j & 3;
    return row * 32 + (((block ^ (row & 7)) << 2) | w);
}

// ---------------- small kernels ----------------
__global__ void k_init(int* perm1, int n1p, int* perm2, int n2p, int* cnt1, int* cnt2) {
    int i = blockIdx.x * blockDim.x + threadIdx.x;
    int stride = gridDim.x * blockDim.x;
    for (int j = i; j < n1p; j += stride) perm1[j] = -1;
    for (int j = i; j < n2p; j += stride) perm2[j] = -1;
    if (i < 8) { cnt1[i] = 0; cnt2[i] = 0; }
}
__global__ void k_hist(const int* __restrict__ off, int n, int* cnt) {
    __shared__ int s[8];
    if (threadIdx.x < 8) s[threadIdx.x] = 0;
    __syncthreads();
    for (int i = blockIdx.x * blockDim.x + threadIdx.x; i < n; i += gridDim.x * blockDim.x)
        atomicAdd(&s[off[i]], 1);
    __syncthreads();
    if (threadIdx.x < 8) atomicAdd(&cnt[threadIdx.x], s[threadIdx.x]);
}
__global__ void k_scan(const int* cnt, int* starts, int* cur) {
    if (threadIdx.x == 0) {
        int run = 0;
        for (int k = 0; k < 8; k++) {
            starts[k] = run; cur[k] = run;
            run += ((cnt[k] + TM - 1) / TM) * TM;
        }
        starts[8] = run;
    }
}
// block-aggregated scatter: 8 global atomics per block instead of per-element
__global__ void k_scatter(const int* __restrict__ off, int n, int* cur, int* perm) {
    __shared__ int s_cnt[8], s_base[8];
    int i = blockIdx.x * blockDim.x + threadIdx.x;
    if (threadIdx.x < 8) s_cnt[threadIdx.x] = 0;
    __syncthreads();
    int bin = 0, r = 0;
    bool valid = (i < n);
    if (valid) { bin = off[i]; r = atomicAdd(&s_cnt[bin], 1); }
    __syncthreads();
    if (threadIdx.x < 8) {
        int c = s_cnt[threadIdx.x];
        s_base[threadIdx.x] = c ? atomicAdd(&cur[threadIdx.x], c) : 0;
    }
    __syncthreads();
    if (valid) perm[s_base[bin] + r] = i;
}

// B2 frag tiles: value B[k][n] = (k<128 ? T2[bin][k][n] : W1[k-128][n]); tf32-rounded
__global__ void k_build_b2(const float* __restrict__ T2, const float* __restrict__ W1, float* B) {
    int idx = blockIdx.x * blockDim.x + threadIdx.x;
    if (idx >= 8 * 192 * DD) return;
    int bin = idx / (192 * DD);
    int k = (idx / DD) % 192;
    int n = idx % DD;
    float v = (k < 128) ? T2[((size_t)bin * 128 + k) * DD + n] : W1[(k - 128) * DD + n];
    int ch = k >> 5, kc = k & 31;
    B[(size_t)(bin * 6 + ch) * 4096 + frag_addr(n, kc)] = tfr(v);
}
// B3 frag tiles: value B[k][n] = (k<256 ? (W3@T3[bin])[k][n] : W2[k-256][n])
__global__ void k_build_b3(const float* __restrict__ W3, const float* __restrict__ T3,
                           const float* __restrict__ W2, float* B) {
    int idx = blockIdx.x * blockDim.x + threadIdx.x;
    if (idx >= 8 * 384 * DD) return;
    int bin = idx / (384 * DD);
    int k = (idx / DD) % 384;
    int n = idx % DD;
    float v;
    if (k < 256) {
        float acc = 0.f;
        const float* w = W3 + (size_t)k * 128;
        const float* t = T3 + (size_t)bin * 128 * DD + n;
#pragma unroll 8
        for (int e = 0; e < 128; e++) acc += w[e] * t[e * DD];
        v = acc;
    } else {
        v = W2[(size_t)(k - 256) * DD + n];
    }
    int ch = k >> 5, kc = k & 31;
    B[(size_t)(bin * 12 + ch) * 4096 + frag_addr(n, kc)] = tfr(v);
}

// ---------------- main gather-GEMM (mma.sync tf32, frag-layout staging) ----------------
// Dynamic smem: bufA[4096] + bufB[2][4096] floats = 48KB
#define SMEM_DYN (12288 * 4)

template <int KTOT, int CSRC, int CFINE>
__global__ __launch_bounds__(256, 2) void k_gemm(
    const float* __restrict__ coarse, const float* __restrict__ fine,
    const float* __restrict__ Btiles, const int* __restrict__ perm,
    const int* __restrict__ parent, const int* __restrict__ starts,
    float* __restrict__ out)
{
    constexpr int NC = KTOT / 32;
    extern __shared__ float smem[];
    float* bufA = smem;          // 4096 floats
    float* bufB = smem + 4096;   // 2 x 4096 floats
    __shared__ int s_gid[128];
    __shared__ const float* s_pc[128];
    __shared__ const float* s_pf[128];
    __shared__ int s_starts[9];

    const int tid = threadIdx.x;
    const int base = blockIdx.x * TM;

    if (tid < 9) s_starts[tid] = starts[tid];
    if (tid < 128) {
        int gd = perm[base + tid];
        s_gid[tid] = gd;
        s_pc[tid] = (gd >= 0) ? coarse + (size_t)parent[gd] * CSRC : nullptr;
        s_pf[tid] = (gd >= 0) ? fine + (size_t)gd * CFINE : nullptr;
    }
    __syncthreads();
    if (base >= s_starts[8]) return;

    int kb = 0;
    while (kb < 7 && base >= s_starts[kb + 1]) kb++;
    const float* Bt = Btiles + (size_t)kb * NC * 4096;

    const int warp = tid >> 5, lane = tid & 31, g = lane >> 2, tg = lane & 3;
    const int wm = warp & 1, wn = warp >> 1;
    const int arow = tid >> 3, aj = tid & 7;   // staging coords: rows arow+32i, j-group aj

    // ---- prologue: reg-load A(0), cp.async B(0) ----
    float4 va[4];
#pragma unroll
    for (int i = 0; i < 4; i++) {
        int row = arow + i * 32;
        const float* sp = s_pc[row];            // chunk 0 always in coarse (CSRC>=128>32... CSRC>0)
        va[i] = sp ? *(const float4*)(sp + 4 * aj) : make_float4(0.f, 0.f, 0.f, 0.f);
    }
#pragma unroll
    for (int i = 0; i < 4; i++)
        cp16(bufB + (tid + i * 256) * 4, Bt + (size_t)(tid + i * 256) * 4);
    cp_commit();

    float acc[4][4][4] = {};

    for (int c = 0; c < NC; c++) {
        const float* Bb = bufB + (c & 1) * 4096;
        __syncthreads();   // compute(c-1) done everywhere
        // ---- STS A(c) in fragment layout (tf32-rounded) ----
#pragma unroll
        for (int i = 0; i < 4; i++) {
            int row = arow + i * 32;
            float v0 = tfr(va[i].x), v1 = tfr(va[i].y), v2 = tfr(va[i].z), v3 = tfr(va[i].w);
            int rb = row * 32, rx = (row & 7) << 2, w = aj & 3, hj = (aj >> 2) << 2;
            bufA[rb + (((0 + hj) ^ rx) | w)] = v0;   // tg=0: block=0+(j>>2)
            bufA[rb + (((8 + hj) ^ rx) | w)] = v1;   // tg=1: block=2+(j>>2)
            bufA[rb + (((16 + hj) ^ rx) | w)] = v2;  // tg=2
            bufA[rb + (((24 + hj) ^ rx) | w)] = v3;  // tg=3
        }
        // ---- cp.async B(c+1) ----
        if (c + 1 < NC) {
            float* bdst = bufB + ((c + 1) & 1) * 4096;
            const float* bsrc = Bt + (size_t)(c + 1) * 4096;
#pragma unroll
            for (int i = 0; i < 4; i++)
                cp16(bdst + (tid + i * 256) * 4, bsrc + (size_t)(tid + i * 256) * 4);
        }
        cp_commit();
        cp_wait1();        // B(c) resident
        // ---- reg-load A(c+1) ----
        if (c + 1 < NC) {
            const int kk = (c + 1) * 32;
#pragma unroll
            for (int i = 0; i < 4; i++) {
                int row = arow + i * 32;
                const float* sp = (kk < CSRC) ? (s_pc[row] ? s_pc[row] + kk : nullptr)
                                              : (s_pf[row] ? s_pf[row] + (kk - CSRC) : nullptr);
                va[i] = sp ? *(const float4*)(sp + 4 * aj) : make_float4(0.f, 0.f, 0.f, 0.f);
            }
        }
        __syncthreads();   // bufA(c) + bufB(c) visible
        // ---- compute chunk c: 64 MMAs via LDS.128 fragment loads ----
#pragma unroll
        for (int h = 0; h < 2; h++) {
            float4 alo[4], ahi[4], bb[4];
            const int pb = ((2 * tg + h) ^ g) << 2;   // phys block offset (row&7 == g)
#pragma unroll
            for (int mt = 0; mt < 4; mt++) {
                int rl = wm * 64 + mt * 16 + g;
                alo[mt] = *(const float4*)(bufA + rl * 32 + pb);
                ahi[mt] = *(const float4*)(bufA + (rl + 8) * 32 + pb);
            }
#pragma unroll
            for (int nt = 0; nt < 4; nt++) {
                int col = wn * 32 + nt * 8 + g;
                bb[nt] = *(const float4*)(Bb + col * 32 + pb);
            }
#pragma unroll
            for (int sel = 0; sel < 2; sel++) {
#pragma unroll
                for (int mt = 0; mt < 4; mt++) {
                    uint32_t af[4];
                    const float* al = (const float*)&alo[mt];
                    const float* ah = (const float*)&ahi[mt];
                    af[0] = __float_as_uint(al[2 * sel]);
                    af[1] = __float_as_uint(ah[2 * sel]);
                    af[2] = __float_as_uint(al[2 * sel + 1]);
                    af[3] = __float_as_uint(ah[2 * sel + 1]);
#pragma unroll
                    for (int nt = 0; nt < 4; nt++) {
                        uint32_t bf[2];
                        const float* bp = (const float*)&bb[nt];
                        bf[0] = __float_as_uint(bp[2 * sel]);
                        bf[1] = __float_as_uint(bp[2 * sel + 1]);
                        mma_tf32(acc[mt][nt], af, bf);
                    }
                }
            }
        }
    }

    // ---- epilogue: scatter store ----
#pragma unroll
    for (int mt = 0; mt < 4; mt++) {
        int row = wm * 64 + mt * 16 + g;
        int g0 = s_gid[row], g1 = s_gid[row + 8];
#pragma unroll
        for (int nt = 0; nt < 4; nt++) {
            int col = wn * 32 + nt * 8 + tg * 2;
            if (g0 >= 0)
                *(float2*)(out + (size_t)g0 * DD + col) =
                    make_float2(acc[mt][nt][0], acc[mt][nt][1]);
            if (g1 >= 0)
                *(float2*)(out + (size_t)g1 * DD + col) =
                    make_float2(acc[mt][nt][2], acc[mt][nt][3]);
        }
    }
}

// ---------------- launch ----------------
extern "C" void kernel_launch(void* const* d_in, const int* in_sizes, int n_in,
                              void* d_out, int out_size)
{
    const float* feats1  = (const float*)d_in[0];
    const float* feats2  = (const float*)d_in[1];
    const float* feats3  = (const float*)d_in[2];
    const int*   parent1 = (const int*)d_in[3];
    const int*   offset1 = (const int*)d_in[4];
    const int*   parent2 = (const int*)d_in[5];
    const int*   offset2 = (const int*)d_in[6];
    const float* W1 = (const float*)d_in[7];
    const float* W2 = (const float*)d_in[8];
    const float* W3 = (const float*)d_in[9];
    const float* T2 = (const float*)d_in[10];
    const float* T3 = (const float*)d_in[11];

    const int N1 = in_sizes[3];
    const int N2 = in_sizes[5];

    float *y2, *B2, *B3;
    int *perm1, *perm2, *cnt1, *cnt2, *st1, *st2, *cu1, *cu2;
    cudaGetSymbolAddress((void**)&y2, g_y2);
    cudaGetSymbolAddress((void**)&B2, g_B2);
    cudaGetSymbolAddress((void**)&B3, g_B3);
    cudaGetSymbolAddress((void**)&perm1, g_perm1);
    cudaGetSymbolAddress((void**)&perm2, g_perm2);
    cudaGetSymbolAddress((void**)&cnt1, g_cnt1);
    cudaGetSymbolAddress((void**)&cnt2, g_cnt2);
    cudaGetSymbolAddress((void**)&st1, g_st1);
    cudaGetSymbolAddress((void**)&st2, g_st2);
    cudaGetSymbolAddress((void**)&cu1, g_cur1);
    cudaGetSymbolAddress((void**)&cu2, g_cur2);

    cudaFuncSetAttribute(k_gemm<384, C3, C2>,
                         cudaFuncAttributeMaxDynamicSharedMemorySize, SMEM_DYN);
    cudaFuncSetAttribute(k_gemm<192, C2, C1>,
                         cudaFuncAttributeMaxDynamicSharedMemorySize, SMEM_DYN);

    const int tiles1 = (N1 + TM - 1) / TM + 8;
    const int tiles2 = (N2 + TM - 1) / TM + 8;
    const int n1p = tiles1 * TM;
    const int n2p = tiles2 * TM;

    k_init<<<512, 256>>>(perm1, n1p, perm2, n2p, cnt1, cnt2);
    k_hist<<<256, 256>>>(offset2, N2, cnt2);
    k_hist<<<512, 256>>>(offset1, N1, cnt1);
    k_scan<<<1, 32>>>(cnt2, st2, cu2);
    k_scan<<<1, 32>>>(cnt1, st1, cu1);
    k_scatter<<<(N2 + 255) / 256, 256>>>(offset2, N2, cu2, perm2);
    k_scatter<<<(N1 + 255) / 256, 256>>>(offset1, N1, cu1, perm1);
    k_build_b2<<<(8 * 192 * DD + 255) / 256, 256>>>(T2, W1, B2);
    k_build_b3<<<(8 * 384 * DD + 255) / 256, 256>>>(W3, T3, W2, B3);

    // level 3 -> 2 : y2 = gather_tconv(feats3@W3, T3) + feats2@W2
    k_gemm<384, C3, C2><<<tiles2, 256, SMEM_DYN>>>(feats3, feats2, B3, perm2, parent2, st2, y2);
    // level 2 -> 1 : out = gather_tconv(y2, T2) + feats1@W1
    k_gemm<192, C2, C1><<<tiles1, 256, SMEM_DYN>>>(y2, feats1, B2, perm1, parent1, st1, (float*)d_out);
}

// round 6
// speedup vs baseline: 2.0126x; 2.0126x over previous
#include <cuda_runtime.h>
#include <cuda_fp16.h>
#include <cstdint>

#define C1 64
#define C2 128
#define C3 256
#define DD 128
#define TM 128

// ---------------- static device scratch (no allocs allowed) ----------------
__device__ float  g_y2[(size_t)131072 * DD];     // level-2 merged features (fp32)
__device__ float  g_y3[(size_t)30720 * DD];      // y3 = feats3 @ W3 (fp32)
__device__ int    g_perm1[420000 + 4096];
__device__ int    g_perm2[131072 + 4096];
__device__ __half g_B3h[8 * 8 * 4096];           // [bin][chunk][n][k swizzled] fp16
__device__ __half g_B2h[8 * 6 * 4096];
__device__ __half g_Bw3h[8 * 4096];              // W3 chunks for y3 GEMM
__device__ int    g_cnt1[8], g_cnt2[8];
__device__ int    g_st1[9], g_st2[9];
__device__ int    g_cur1[8], g_cur2[8];

// ---------------- helpers ----------------
__device__ __forceinline__ uint32_t smem_u32(const void* p) {
    uint32_t a;
    asm("{ .reg .u64 t; cvta.to.shared.u64 t, %1; cvt.u32.u64 %0, t; }" : "=r"(a) : "l"(p));
    return a;
}
__device__ __forceinline__ void cp16(void* dst_smem, const void* src) {
    uint32_t d = smem_u32(dst_smem);
    asm volatile("cp.async.ca.shared.global [%0], [%1], 16;" :: "r"(d), "l"(src) : "memory");
}
__device__ __forceinline__ void cp_commit() { asm volatile("cp.async.commit_group;" ::: "memory"); }
__device__ __forceinline__ void cp_wait0()  { asm volatile("cp.async.wait_group 0;" ::: "memory"); }

__device__ __forceinline__ uint32_t pk(float a, float b) {
    __half2 h = __floats2half2_rn(a, b);
    return *(uint32_t*)&h;
}
__device__ __forceinline__ void ldsm4(uint32_t* r, uint32_t addr) {
    asm volatile("ldmatrix.sync.aligned.m8n8.x4.shared.b16 {%0,%1,%2,%3}, [%4];"
                 : "=r"(r[0]), "=r"(r[1]), "=r"(r[2]), "=r"(r[3]) : "r"(addr));
}
__device__ __forceinline__ void mma_f16(float* c, const uint32_t* a, const uint32_t* b) {
    asm volatile(
        "mma.sync.aligned.m16n8k16.row.col.f32.f16.f16.f32 "
        "{%0,%1,%2,%3}, {%4,%5,%6,%7}, {%8,%9}, {%0,%1,%2,%3};\n"
        : "+f"(c[0]), "+f"(c[1]), "+f"(c[2]), "+f"(c[3])
        : "r"(a[0]), "r"(a[1]), "r"(a[2]), "r"(a[3]), "r"(b[0]), "r"(b[1]));
}

// swizzled half-index within a 128x32-half chunk tile (rows of 64B, XOR on 16B blocks)
__device__ __forceinline__ int swz_pos(int row, int kc) {
    return row * 32 + ((((kc >> 3) & 3) ^ ((row >> 1) & 3)) << 3) + (kc & 7);
}

// ---------------- prep: init perms, zero counters, convert W3 to fp16 tiles ----------------
__global__ void k_prep(int* perm1, int n1p, int* perm2, int n2p, int* cnt1, int* cnt2,
                       const float* __restrict__ W3, __half* Bw3h) {
    int i = blockIdx.x * blockDim.x + threadIdx.x;
    int stride = gridDim.x * blockDim.x;
    for (int j = i; j < n1p; j += stride) perm1[j] = -1;
    for (int j = i; j < n2p; j += stride) perm2[j] = -1;
    if (i < 8) { cnt1[i] = 0; cnt2[i] = 0; }
    for (int j = i; j < 256 * 128; j += stride) {
        int k = j >> 7, n = j & 127;
        int ch = k >> 5, kc = k & 31;
        Bw3h[ch * 4096 + swz_pos(n, kc)] = __float2half_rn(W3[(size_t)k * 128 + n]);
    }
}

__global__ void k_hist2(const int* __restrict__ off1, int n1,
                        const int* __restrict__ off2, int n2, int* cnt1, int* cnt2) {
    __shared__ int s[16];
    if (threadIdx.x < 16) s[threadIdx.x] = 0;
    __syncthreads();
    int stride = gridDim.x * blockDim.x;
    for (int i = blockIdx.x * blockDim.x + threadIdx.x; i < n1; i += stride) atomicAdd(&s[off1[i]], 1);
    for (int i = blockIdx.x * blockDim.x + threadIdx.x; i < n2; i += stride) atomicAdd(&s[8 + off2[i]], 1);
    __syncthreads();
    if (threadIdx.x < 8) atomicAdd(&cnt1[threadIdx.x], s[threadIdx.x]);
    else if (threadIdx.x < 16) atomicAdd(&cnt2[threadIdx.x - 8], s[threadIdx.x]);
}

__global__ void k_scan2(const int* cnt1, int* st1, int* cur1,
                        const int* cnt2, int* st2, int* cur2) {
    if (threadIdx.x == 0) {
        int run = 0;
        for (int k = 0; k < 8; k++) { st1[k] = run; cur1[k] = run; run += ((cnt1[k] + TM - 1) / TM) * TM; }
        st1[8] = run;
        run = 0;
        for (int k = 0; k < 8; k++) { st2[k] = run; cur2[k] = run; run += ((cnt2[k] + TM - 1) / TM) * TM; }
        st2[8] = run;
    }
}

__global__ void k_scat2(const int* __restrict__ off1, int n1,
                        const int* __restrict__ off2, int n2,
                        int* cur1, int* cur2, int* perm1, int* perm2) {
    __shared__ int s_cnt[16], s_base[16];
    int i = blockIdx.x * blockDim.x + threadIdx.x;
    if (threadIdx.x < 16) s_cnt[threadIdx.x] = 0;
    __syncthreads();
    int slot = -1, r = 0;
    if (i < n1)            { slot = off1[i];          r = atomicAdd(&s_cnt[slot], 1); }
    else if (i < n1 + n2)  { slot = 8 + off2[i - n1]; r = atomicAdd(&s_cnt[slot], 1); }
    __syncthreads();
    if (threadIdx.x < 16) {
        int c = s_cnt[threadIdx.x];
        if (c) s_base[threadIdx.x] = (threadIdx.x < 8)
            ? atomicAdd(&cur1[threadIdx.x], c) : atomicAdd(&cur2[threadIdx.x - 8], c);
    }
    __syncthreads();
    if (slot >= 0) {
        if (slot < 8) perm1[s_base[slot] + r] = i;
        else          perm2[s_base[slot] + r] = i - n1;
    }
}

// build fp16 B tiles: B3 = [T3k ; W2] (K=256), B2 = [T2k ; W1] (K=192)
__global__ void k_build(const float* __restrict__ T2, const float* __restrict__ W1,
                        const float* __restrict__ T3, const float* __restrict__ W2,
                        __half* B2h, __half* B3h) {
    int idx = blockIdx.x * blockDim.x + threadIdx.x;
    const int NB3 = 8 * 256 * 128;
    if (idx < NB3) {
        int bin = idx / (256 * 128);
        int k = (idx >> 7) % 256;
        int n = idx & 127;
        float v = (k < 128) ? T3[((size_t)bin * 128 + k) * 128 + n] : W2[(size_t)(k - 128) * 128 + n];
        int ch = k >> 5, kc = k & 31;
        B3h[(bin * 8 + ch) * 4096 + swz_pos(n, kc)] = __float2half_rn(v);
    } else {
        idx -= NB3;
        if (idx >= 8 * 192 * 128) return;
        int bin = idx / (192 * 128);
        int k = (idx >> 7) % 192;
        int n = idx & 127;
        float v = (k < 128) ? T2[((size_t)bin * 128 + k) * 128 + n] : W1[(size_t)(k - 128) * 128 + n];
        int ch = k >> 5, kc = k & 31;
        B2h[(bin * 6 + ch) * 4096 + swz_pos(n, kc)] = __float2half_rn(v);
    }
}

// ---------------- main gather-GEMM (fp16 mma.sync m16n8k16) ----------------
// dynamic smem 32KB: A[2][8KB] at 0, B[2][8KB] at 16384
template <int KTOT, int CSRC, int CFINE, bool DENSE>
__global__ __launch_bounds__(256, 2) void k_gemm(
    const float* __restrict__ coarse, const float* __restrict__ fine,
    const __half* __restrict__ Btiles, const int* __restrict__ perm,
    const int* __restrict__ parent, const int* __restrict__ starts,
    int nrows, int tile0, float* __restrict__ out)
{
    constexpr int NC = KTOT / 32;
    extern __shared__ char smemc[];
    __shared__ int s_gid[128];
    __shared__ const float* s_pc[128];
    __shared__ const float* s_pf[128];
    __shared__ int s_starts[9];

    const int tid = threadIdx.x;
    const int base = (tile0 + blockIdx.x) * TM;

    if (DENSE) {
        if (tid < 128) {
            int gid = (base + tid < nrows) ? base + tid : -1;
            s_gid[tid] = gid;
            s_pc[tid] = (gid >= 0) ? coarse + (size_t)gid * CSRC : nullptr;
        }
    } else {
        if (tid < 9) s_starts[tid] = starts[tid];
        if (tid < 128) {
            int gd = perm[base + tid];
            s_gid[tid] = gd;
            s_pc[tid] = (gd >= 0) ? coarse + (size_t)parent[gd] * CSRC : nullptr;
            s_pf[tid] = (gd >= 0) ? fine + (size_t)gd * CFINE : nullptr;
        }
    }
    __syncthreads();

    const __half* Bt = Btiles;
    if (!DENSE) {
        if (base >= s_starts[8]) return;
        int kb = 0;
        while (kb < 7 && base >= s_starts[kb + 1]) kb++;
        Bt = Btiles + (size_t)kb * NC * 4096;
    }

    const uint32_t uA = smem_u32(smemc);
    const uint32_t uB = uA + 16384;

    // ---- staging ids: one thread = one (row, 16-half segment) ----
    const int srow = tid >> 1, sseg = tid & 1;
    const float* pc = s_pc[srow];
    const float* pf = DENSE ? nullptr : s_pf[srow];
    const int srx = (srow >> 1) & 3;
    const uint32_t sts0 = srow * 64 + (((sseg * 2)     ^ srx) << 4);
    const uint32_t sts1 = srow * 64 + (((sseg * 2 + 1) ^ srx) << 4);

    // ---- compute-lane fragment addressing ----
    const int warp = tid >> 5, lane = tid & 31;
    const int wm = warp & 1, wn = warp >> 1;
    const int alrow = (lane & 7) + ((lane >> 3) & 1) * 8;
    const int akb = lane >> 4;                 // 0/1 k-block offset
    uint32_t a_row[4]; int a_rx[4];
#pragma unroll
    for (int mt = 0; mt < 4; mt++) {
        int r = wm * 64 + mt * 16 + alrow;
        a_row[mt] = uA + r * 64;
        a_rx[mt] = (r >> 1) & 3;
    }
    const int blrow = (lane & 7) + ((lane >> 4) << 3);
    const int bkb = (lane >> 3) & 1;
    uint32_t b_row[2]; int b_rx[2];
#pragma unroll
    for (int p = 0; p < 2; p++) {
        int n = wn * 32 + p * 16 + blrow;
        b_row[p] = uB + n * 64;
        b_rx[p] = (n >> 1) & 3;
    }

    float4 va[4];
#define LDGA(c) { \
        const int kk = (c) * 32 + sseg * 16; \
        const float* sp; \
        if (DENSE) sp = pc ? pc + kk : nullptr; \
        else if (kk < CSRC) sp = pc ? pc + kk : nullptr; \
        else sp = pf ? pf + (kk - CSRC) : nullptr; \
        if (sp) { va[0] = *(const float4*)sp; va[1] = *(const float4*)(sp + 4); \
                  va[2] = *(const float4*)(sp + 8); va[3] = *(const float4*)(sp + 12); } \
        else { va[0] = va[1] = va[2] = va[3] = make_float4(0.f, 0.f, 0.f, 0.f); } }

    // ---- prologue: A(0) to regs, B(0) via cp.async ----
    LDGA(0);
    {
        const char* bs = (const char*)Bt;
        char* bd = smemc + 16384;
        cp16(bd + tid * 32, bs + tid * 32);
        cp16(bd + tid * 32 + 16, bs + tid * 32 + 16);
        cp_commit();
    }

    float acc[4][4][4] = {};

    for (int c = 0; c < NC; c++) {
        const uint32_t boff = (uint32_t)(c & 1) * 8192u;
        // STS A(c) fp16-swizzled (buffer c&1; disjoint from compute(c-1)'s buffer)
        {
            uint4 w0 = make_uint4(pk(va[0].x, va[0].y), pk(va[0].z, va[0].w),
                                  pk(va[1].x, va[1].y), pk(va[1].z, va[1].w));
            uint4 w1 = make_uint4(pk(va[2].x, va[2].y), pk(va[2].z, va[2].w),
                                  pk(va[3].x, va[3].y), pk(va[3].z, va[3].w));
            *(uint4*)(smemc + boff + sts0) = w0;
            *(uint4*)(smemc + boff + sts1) = w1;
        }
        if (c + 1 < NC) LDGA(c + 1);
        // B(c) complete per-thread, THEN barrier -> all threads' B(c)+A(c) visible.
        cp_wait0();
        __syncthreads();
        // Issue B(c+1) after the barrier (compute(c-1) everywhere has finished
        // reading buffer (c+1)&1); overlaps with compute(c).
        if (c + 1 < NC) {
            const char* bs = (const char*)Bt + (size_t)(c + 1) * 8192;
            char* bd = smemc + 16384 + ((c + 1) & 1) * 8192;
            cp16(bd + tid * 32, bs + tid * 32);
            cp16(bd + tid * 32 + 16, bs + tid * 32 + 16);
            cp_commit();
        }
        // ---- compute chunk c: 12 ldmatrix.x4 + 32 mma ----
#pragma unroll
        for (int kb16 = 0; kb16 < 2; kb16++) {
            const int klo = kb16 * 2;
            uint32_t bf[2][4];
#pragma unroll
            for (int p = 0; p < 2; p++)
                ldsm4(bf[p], b_row[p] + boff + (((klo + bkb) ^ b_rx[p]) << 4));
#pragma unroll
            for (int mt = 0; mt < 4; mt++) {
                uint32_t af[4];
                ldsm4(af, a_row[mt] + boff + (((klo + akb) ^ a_rx[mt]) << 4));
#pragma unroll
                for (int nt = 0; nt < 4; nt++)
                    mma_f16(acc[mt][nt], af, &bf[nt >> 1][(nt & 1) * 2]);
            }
        }
    }

    // ---- epilogue: scatter store (fp32) ----
    const int g = lane >> 2, tg = lane & 3;
#pragma unroll
    for (int mt = 0; mt < 4; mt++) {
        int row = wm * 64 + mt * 16 + g;
        int g0 = s_gid[row], g1 = s_gid[row + 8];
#pragma unroll
        for (int nt = 0; nt < 4; nt++) {
            int col = wn * 32 + nt * 8 + tg * 2;
            if (g0 >= 0)
                *(float2*)(out + (size_t)g0 * DD + col) = make_float2(acc[mt][nt][0], acc[mt][nt][1]);
            if (g1 >= 0)
                *(float2*)(out + (size_t)g1 * DD + col) = make_float2(acc[mt][nt][2], acc[mt][nt][3]);
        }
    }
#undef LDGA
}

// ---------------- launch ----------------
extern "C" void kernel_launch(void* const* d_in, const int* in_sizes, int n_in,
                              void* d_out, int out_size)
{
    const float* feats1  = (const float*)d_in[0];
    const float* feats2  = (const float*)d_in[1];
    const float* feats3  = (const float*)d_in[2];
    const int*   parent1 = (const int*)d_in[3];
    const int*   offset1 = (const int*)d_in[4];
    const int*   parent2 = (const int*)d_in[5];
    const int*   offset2 = (const int*)d_in[6];
    const float* W1 = (const float*)d_in[7];
    const float* W2 = (const float*)d_in[8];
    const float* W3 = (const float*)d_in[9];
    const float* T2 = (const float*)d_in[10];
    const float* T3 = (const float*)d_in[11];

    const int N1 = in_sizes[3];
    const int N2 = in_sizes[5];
    const int N3 = in_sizes[2] / C3;

    float *y2, *y3;
    __half *B2h, *B3h, *Bw3h;
    int *perm1, *perm2, *cnt1, *cnt2, *st1, *st2, *cu1, *cu2;
    cudaGetSymbolAddress((void**)&y2, g_y2);
    cudaGetSymbolAddress((void**)&y3, g_y3);
    cudaGetSymbolAddress((void**)&B2h, g_B2h);
    cudaGetSymbolAddress((void**)&B3h, g_B3h);
    cudaGetSymbolAddress((void**)&Bw3h, g_Bw3h);
    cudaGetSymbolAddress((void**)&perm1, g_perm1);
    cudaGetSymbolAddress((void**)&perm2, g_perm2);
    cudaGetSymbolAddress((void**)&cnt1, g_cnt1);
    cudaGetSymbolAddress((void**)&cnt2, g_cnt2);
    cudaGetSymbolAddress((void**)&st1, g_st1);
    cudaGetSymbolAddress((void**)&st2, g_st2);
    cudaGetSymbolAddress((void**)&cu1, g_cur1);
    cudaGetSymbolAddress((void**)&cu2, g_cur2);

    const int tiles1 = (N1 + TM - 1) / TM + 8;
    const int tiles2 = (N2 + TM - 1) / TM + 8;
    const int n1p = tiles1 * TM;
    const int n2p = tiles2 * TM;
    const int tiles3 = (N3 + TM - 1) / TM;
    const int t3a = (tiles3 + 1) / 2, t3b = tiles3 - t3a;

    // launches 1-3: prep chain
    k_prep<<<512, 256>>>(perm1, n1p, perm2, n2p, cnt1, cnt2, W3, Bw3h);
    k_hist2<<<512, 256>>>(offset1, N1, offset2, N2, cnt1, cnt2);
    k_scan2<<<1, 32>>>(cnt1, st1, cu1, cnt2, st2, cu2);
    // launches 4,5: y3 = feats3 @ W3 (dense, split so ncu -s captures a GEMM)
    k_gemm<256, C3, 1, true><<<t3a, 256, 32768>>>(feats3, nullptr, Bw3h,
        nullptr, nullptr, nullptr, N3, 0, y3);
    k_gemm<256, C3, 1, true><<<t3b, 256, 32768>>>(feats3, nullptr, Bw3h,
        nullptr, nullptr, nullptr, N3, t3a, y3);
    // launches 6,7: scatter + B builds
    k_scat2<<<(N1 + N2 + 255) / 256, 256>>>(offset1, N1, offset2, N2, cu1, cu2, perm1, perm2);
    k_build<<<(8 * 256 * 128 + 8 * 192 * 128 + 255) / 256, 256>>>(T2, W1, T3, W2, B2h, B3h);
    // launch 8: y2 = gather_tconv(y3, T3) + feats2 @ W2
    k_gemm<256, C2, C2, false><<<tiles2, 256, 32768>>>(y3, feats2, B3h,
        perm2, parent2, st2, 0, 0, y2);
    // launch 9: out = gather_tconv(y2, T2) + feats1 @ W1
    k_gemm<192, C2, C1, false><<<tiles1, 256, 32768>>>(y2, feats1, B2h,
        perm1, parent1, st1, 0, 0, (float*)d_out);
}

// round 7
// speedup vs baseline: 2.1701x; 1.0782x over previous
#include <cuda_runtime.h>
#include <cuda_fp16.h>
#include <cstdint>

#define C1 64
#define C2 128
#define C3 256
#define DD 128
#define TM 128

// ---------------- static device scratch (no allocs allowed) ----------------
__device__ __half g_y2h[(size_t)131072 * DD];    // level-2 merged features (fp16)
__device__ __half g_y3h[(size_t)30720 * DD];     // y3 = feats3 @ W3 (fp16)
__device__ int    g_perm1[420000 + 4096];
__device__ int    g_perm2[131072 + 4096];
__device__ __half g_B3h[8 * 8 * 4096];           // [bin][chunk][n][k swizzled] fp16
__device__ __half g_B2h[8 * 6 * 4096];
__device__ __half g_Bw3h[8 * 4096];              // W3 chunks for y3 GEMM
__device__ int    g_cnt1[8], g_cnt2[8];
__device__ int    g_st1[9], g_st2[9];
__device__ int    g_cur1[8], g_cur2[8];

// ---------------- helpers ----------------
__device__ __forceinline__ uint32_t smem_u32(const void* p) {
    uint32_t a;
    asm("{ .reg .u64 t; cvta.to.shared.u64 t, %1; cvt.u32.u64 %0, t; }" : "=r"(a) : "l"(p));
    return a;
}
__device__ __forceinline__ void cp16(void* dst_smem, const void* src) {
    uint32_t d = smem_u32(dst_smem);
    asm volatile("cp.async.ca.shared.global [%0], [%1], 16;" :: "r"(d), "l"(src) : "memory");
}
__device__ __forceinline__ void cp_commit() { asm volatile("cp.async.commit_group;" ::: "memory"); }
__device__ __forceinline__ void cp_wait0()  { asm volatile("cp.async.wait_group 0;" ::: "memory"); }

__device__ __forceinline__ uint32_t pk(float a, float b) {
    __half2 h = __floats2half2_rn(a, b);
    return *(uint32_t*)&h;
}
__device__ __forceinline__ void ldsm4(uint32_t* r, uint32_t addr) {
    asm volatile("ldmatrix.sync.aligned.m8n8.x4.shared.b16 {%0,%1,%2,%3}, [%4];"
                 : "=r"(r[0]), "=r"(r[1]), "=r"(r[2]), "=r"(r[3]) : "r"(addr));
}
__device__ __forceinline__ void mma_f16(float* c, const uint32_t* a, const uint32_t* b) {
    asm volatile(
        "mma.sync.aligned.m16n8k16.row.col.f32.f16.f16.f32 "
        "{%0,%1,%2,%3}, {%4,%5,%6,%7}, {%8,%9}, {%0,%1,%2,%3};\n"
        : "+f"(c[0]), "+f"(c[1]), "+f"(c[2]), "+f"(c[3])
        : "r"(a[0]), "r"(a[1]), "r"(a[2]), "r"(a[3]), "r"(b[0]), "r"(b[1]));
}

// swizzled half-index within a 128x32-half chunk tile (rows of 64B, XOR on 16B blocks)
__device__ __forceinline__ int swz_pos(int row, int kc) {
    return row * 32 + ((((kc >> 3) & 3) ^ ((row >> 1) & 3)) << 3) + (kc & 7);
}

// ---------------- prep: init perms, zero counters, convert W3 to fp16 tiles ----------------
__global__ void k_prep(int* perm1, int n1p, int* perm2, int n2p, int* cnt1, int* cnt2,
                       const float* __restrict__ W3, __half* Bw3h) {
    int i = blockIdx.x * blockDim.x + threadIdx.x;
    int stride = gridDim.x * blockDim.x;
    for (int j = i; j < n1p; j += stride) perm1[j] = -1;
    for (int j = i; j < n2p; j += stride) perm2[j] = -1;
    if (i < 8) { cnt1[i] = 0; cnt2[i] = 0; }
    for (int j = i; j < 256 * 128; j += stride) {
        int k = j >> 7, n = j & 127;
        int ch = k >> 5, kc = k & 31;
        Bw3h[ch * 4096 + swz_pos(n, kc)] = __float2half_rn(W3[(size_t)k * 128 + n]);
    }
}

__global__ void k_hist2(const int* __restrict__ off1, int n1,
                        const int* __restrict__ off2, int n2, int* cnt1, int* cnt2) {
    __shared__ int s[16];
    if (threadIdx.x < 16) s[threadIdx.x] = 0;
    __syncthreads();
    int stride = gridDim.x * blockDim.x;
    for (int i = blockIdx.x * blockDim.x + threadIdx.x; i < n1; i += stride) atomicAdd(&s[off1[i]], 1);
    for (int i = blockIdx.x * blockDim.x + threadIdx.x; i < n2; i += stride) atomicAdd(&s[8 + off2[i]], 1);
    __syncthreads();
    if (threadIdx.x < 8) atomicAdd(&cnt1[threadIdx.x], s[threadIdx.x]);
    else if (threadIdx.x < 16) atomicAdd(&cnt2[threadIdx.x - 8], s[threadIdx.x]);
}

__global__ void k_scan2(const int* cnt1, int* st1, int* cur1,
                        const int* cnt2, int* st2, int* cur2) {
    if (threadIdx.x == 0) {
        int run = 0;
        for (int k = 0; k < 8; k++) { st1[k] = run; cur1[k] = run; run += ((cnt1[k] + TM - 1) / TM) * TM; }
        st1[8] = run;
        run = 0;
        for (int k = 0; k < 8; k++) { st2[k] = run; cur2[k] = run; run += ((cnt2[k] + TM - 1) / TM) * TM; }
        st2[8] = run;
    }
}

__global__ void k_scat2(const int* __restrict__ off1, int n1,
                        const int* __restrict__ off2, int n2,
                        int* cur1, int* cur2, int* perm1, int* perm2) {
    __shared__ int s_cnt[16], s_base[16];
    int i = blockIdx.x * blockDim.x + threadIdx.x;
    if (threadIdx.x < 16) s_cnt[threadIdx.x] = 0;
    __syncthreads();
    int slot = -1, r = 0;
    if (i < n1)            { slot = off1[i];          r = atomicAdd(&s_cnt[slot], 1); }
    else if (i < n1 + n2)  { slot = 8 + off2[i - n1]; r = atomicAdd(&s_cnt[slot], 1); }
    __syncthreads();
    if (threadIdx.x < 16) {
        int c = s_cnt[threadIdx.x];
        if (c) s_base[threadIdx.x] = (threadIdx.x < 8)
            ? atomicAdd(&cur1[threadIdx.x], c) : atomicAdd(&cur2[threadIdx.x - 8], c);
    }
    __syncthreads();
    if (slot >= 0) {
        if (slot < 8) perm1[s_base[slot] + r] = i;
        else          perm2[s_base[slot] + r] = i - n1;
    }
}

// build fp16 B tiles: B3 = [T3k ; W2] (K=256), B2 = [T2k ; W1] (K=192)
__global__ void k_build(const float* __restrict__ T2, const float* __restrict__ W1,
                        const float* __restrict__ T3, const float* __restrict__ W2,
                        __half* B2h, __half* B3h) {
    int idx = blockIdx.x * blockDim.x + threadIdx.x;
    const int NB3 = 8 * 256 * 128;
    if (idx < NB3) {
        int bin = idx / (256 * 128);
        int k = (idx >> 7) % 256;
        int n = idx & 127;
        float v = (k < 128) ? T3[((size_t)bin * 128 + k) * 128 + n] : W2[(size_t)(k - 128) * 128 + n];
        int ch = k >> 5, kc = k & 31;
        B3h[(bin * 8 + ch) * 4096 + swz_pos(n, kc)] = __float2half_rn(v);
    } else {
        idx -= NB3;
        if (idx >= 8 * 192 * 128) return;
        int bin = idx / (192 * 128);
        int k = (idx >> 7) % 192;
        int n = idx & 127;
        float v = (k < 128) ? T2[((size_t)bin * 128 + k) * 128 + n] : W1[(size_t)(k - 128) * 128 + n];
        int ch = k >> 5, kc = k & 31;
        B2h[(bin * 6 + ch) * 4096 + swz_pos(n, kc)] = __float2half_rn(v);
    }
}

// ---------------- main gather-GEMM (fp16 mma.sync m16n8k16) ----------------
// dynamic smem 32KB: A[2][8KB] at 0, B[2][8KB] at 16384
// HC: coarse (gathered) source is fp16; HO: output stored as fp16
template <int KTOT, int CSRC, int CFINE, bool DENSE, bool HC, bool HO>
__global__ __launch_bounds__(256, 2) void k_gemm(
    const void* __restrict__ coarse_, const float* __restrict__ fine,
    const __half* __restrict__ Btiles, const int* __restrict__ perm,
    const int* __restrict__ parent, const int* __restrict__ starts,
    int nrows, int tile0, void* __restrict__ out_)
{
    constexpr int NC = KTOT / 32;
    constexpr int CEB = HC ? 2 : 4;   // coarse element bytes
    extern __shared__ char smemc[];
    __shared__ int s_gid[128];
    __shared__ const char* s_pc[128];
    __shared__ const float* s_pf[128];
    __shared__ int s_starts[9];

    const int tid = threadIdx.x;
    const int base = (tile0 + blockIdx.x) * TM;

    if (DENSE) {
        if (tid < 128) {
            int gid = (base + tid < nrows) ? base + tid : -1;
            s_gid[tid] = gid;
            s_pc[tid] = (gid >= 0) ? (const char*)coarse_ + (size_t)gid * CSRC * CEB : nullptr;
        }
    } else {
        if (tid < 9) s_starts[tid] = starts[tid];
        if (tid < 128) {
            int gd = perm[base + tid];
            s_gid[tid] = gd;
            s_pc[tid] = (gd >= 0) ? (const char*)coarse_ + (size_t)parent[gd] * CSRC * CEB : nullptr;
            s_pf[tid] = (gd >= 0) ? fine + (size_t)gd * CFINE : nullptr;
        }
    }
    __syncthreads();

    const __half* Bt = Btiles;
    if (!DENSE) {
        if (base >= s_starts[8]) return;
        int kb = 0;
        while (kb < 7 && base >= s_starts[kb + 1]) kb++;
        Bt = Btiles + (size_t)kb * NC * 4096;
    }

    const uint32_t uA = smem_u32(smemc);
    const uint32_t uB = uA + 16384;

    // ---- staging ids: one thread = one (row, 16-element k segment) ----
    const int srow = tid >> 1, sseg = tid & 1;
    const char* pc = s_pc[srow];
    const float* pf = DENSE ? nullptr : s_pf[srow];
    const int srx = (srow >> 1) & 3;
    const uint32_t sts0 = srow * 64 + (((sseg * 2)     ^ srx) << 4);
    const uint32_t sts1 = srow * 64 + (((sseg * 2 + 1) ^ srx) << 4);

    // ---- compute-lane fragment addressing ----
    const int warp = tid >> 5, lane = tid & 31;
    const int wm = warp & 1, wn = warp >> 1;
    const int alrow = (lane & 7) + ((lane >> 3) & 1) * 8;
    const int akb = lane >> 4;                 // 0/1 k-block offset
    uint32_t a_row[4]; int a_rx[4];
#pragma unroll
    for (int mt = 0; mt < 4; mt++) {
        int r = wm * 64 + mt * 16 + alrow;
        a_row[mt] = uA + r * 64;
        a_rx[mt] = (r >> 1) & 3;
    }
    const int blrow = (lane & 7) + ((lane >> 4) << 3);
    const int bkb = (lane >> 3) & 1;
    uint32_t b_row[2]; int b_rx[2];
#pragma unroll
    for (int p = 0; p < 2; p++) {
        int n = wn * 32 + p * 16 + blrow;
        b_row[p] = uB + n * 64;
        b_rx[p] = (n >> 1) & 3;
    }

    float4 vf0, vf1, vf2, vf3;      // fp32 staging (fine / fp32 coarse)
    uint4  vh0, vh1;                // fp16 staging (fp16 coarse: raw copy)
    const uint4 zero4 = make_uint4(0u, 0u, 0u, 0u);

#define LDGA(c) { \
        const int kk = (c) * 32 + sseg * 16; \
        if (HC && kk < CSRC) { \
            const __half* sp = pc ? (const __half*)pc + kk : nullptr; \
            vh0 = sp ? *(const uint4*)sp : zero4; \
            vh1 = sp ? *(const uint4*)(sp + 8) : zero4; \
        } else { \
            const float* sp; \
            if (!HC && kk < CSRC) sp = pc ? (const float*)pc + kk : nullptr; \
            else                  sp = pf ? pf + (kk - CSRC) : nullptr; \
            if (sp) { vf0 = *(const float4*)sp;       vf1 = *(const float4*)(sp + 4); \
                      vf2 = *(const float4*)(sp + 8); vf3 = *(const float4*)(sp + 12); } \
            else { vf0 = vf1 = vf2 = vf3 = make_float4(0.f, 0.f, 0.f, 0.f); } \
        } }

#define STSA(c) { \
        const int kk = (c) * 32 + sseg * 16; \
        const uint32_t boff_ = (uint32_t)((c) & 1) * 8192u; \
        if (HC && kk < CSRC) { \
            *(uint4*)(smemc + boff_ + sts0) = vh0; \
            *(uint4*)(smemc + boff_ + sts1) = vh1; \
        } else { \
            uint4 w0 = make_uint4(pk(vf0.x, vf0.y), pk(vf0.z, vf0.w), \
                                  pk(vf1.x, vf1.y), pk(vf1.z, vf1.w)); \
            uint4 w1 = make_uint4(pk(vf2.x, vf2.y), pk(vf2.z, vf2.w), \
                                  pk(vf3.x, vf3.y), pk(vf3.z, vf3.w)); \
            *(uint4*)(smemc + boff_ + sts0) = w0; \
            *(uint4*)(smemc + boff_ + sts1) = w1; \
        } }

    // ---- prologue: A(0) to regs, B(0) via cp.async ----
    LDGA(0);
    {
        const char* bs = (const char*)Bt;
        char* bd = smemc + 16384;
        cp16(bd + tid * 32, bs + tid * 32);
        cp16(bd + tid * 32 + 16, bs + tid * 32 + 16);
        cp_commit();
    }

    float acc[4][4][4] = {};

    for (int c = 0; c < NC; c++) {
        const uint32_t boff = (uint32_t)(c & 1) * 8192u;
        STSA(c);                              // A(c) into buffer c&1
        if (c + 1 < NC) LDGA(c + 1);
        // B(c) complete per-thread, THEN barrier -> all threads' B(c)+A(c) visible.
        cp_wait0();
        __syncthreads();
        // Issue B(c+1) after the barrier; overlaps with compute(c).
        if (c + 1 < NC) {
            const char* bs = (const char*)Bt + (size_t)(c + 1) * 8192;
            char* bd = smemc + 16384 + ((c + 1) & 1) * 8192;
            cp16(bd + tid * 32, bs + tid * 32);
            cp16(bd + tid * 32 + 16, bs + tid * 32 + 16);
            cp_commit();
        }
        // ---- compute chunk c: 12 ldmatrix.x4 + 32 mma ----
#pragma unroll
        for (int kb16 = 0; kb16 < 2; kb16++) {
            const int klo = kb16 * 2;
            uint32_t bf[2][4];
#pragma unroll
            for (int p = 0; p < 2; p++)
                ldsm4(bf[p], b_row[p] + boff + (((klo + bkb) ^ b_rx[p]) << 4));
#pragma unroll
            for (int mt = 0; mt < 4; mt++) {
                uint32_t af[4];
                ldsm4(af, a_row[mt] + boff + (((klo + akb) ^ a_rx[mt]) << 4));
#pragma unroll
                for (int nt = 0; nt < 4; nt++)
                    mma_f16(acc[mt][nt], af, &bf[nt >> 1][(nt & 1) * 2]);
            }
        }
    }

    // ---- epilogue: scatter store ----
    const int g = lane >> 2, tg = lane & 3;
#pragma unroll
    for (int mt = 0; mt < 4; mt++) {
        int row = wm * 64 + mt * 16 + g;
        int g0 = s_gid[row], g1 = s_gid[row + 8];
#pragma unroll
        for (int nt = 0; nt < 4; nt++) {
            int col = wn * 32 + nt * 8 + tg * 2;
            if (HO) {
                __half* oh = (__half*)out_;
                if (g0 >= 0)
                    *(uint32_t*)(oh + (size_t)g0 * DD + col) = pk(acc[mt][nt][0], acc[mt][nt][1]);
                if (g1 >= 0)
                    *(uint32_t*)(oh + (size_t)g1 * DD + col) = pk(acc[mt][nt][2], acc[mt][nt][3]);
            } else {
                float* of = (float*)out_;
                if (g0 >= 0)
                    *(float2*)(of + (size_t)g0 * DD + col) = make_float2(acc[mt][nt][0], acc[mt][nt][1]);
                if (g1 >= 0)
                    *(float2*)(of + (size_t)g1 * DD + col) = make_float2(acc[mt][nt][2], acc[mt][nt][3]);
            }
        }
    }
#undef LDGA
#undef STSA
}

// ---------------- launch ----------------
extern "C" void kernel_launch(void* const* d_in, const int* in_sizes, int n_in,
                              void* d_out, int out_size)
{
    const float* feats1  = (const float*)d_in[0];
    const float* feats2  = (const float*)d_in[1];
    const float* feats3  = (const float*)d_in[2];
    const int*   parent1 = (const int*)d_in[3];
    const int*   offset1 = (const int*)d_in[4];
    const int*   parent2 = (const int*)d_in[5];
    const int*   offset2 = (const int*)d_in[6];
    const float* W1 = (const float*)d_in[7];
    const float* W2 = (const float*)d_in[8];
    const float* W3 = (const float*)d_in[9];
    const float* T2 = (const float*)d_in[10];
    const float* T3 = (const float*)d_in[11];

    const int N1 = in_sizes[3];
    const int N2 = in_sizes[5];
    const int N3 = in_sizes[2] / C3;

    __half *y2h, *y3h, *B2h, *B3h, *Bw3h;
    int *perm1, *perm2, *cnt1, *cnt2, *st1, *st2, *cu1, *cu2;
    cudaGetSymbolAddress((void**)&y2h, g_y2h);
    cudaGetSymbolAddress((void**)&y3h, g_y3h);
    cudaGetSymbolAddress((void**)&B2h, g_B2h);
    cudaGetSymbolAddress((void**)&B3h, g_B3h);
    cudaGetSymbolAddress((void**)&Bw3h, g_Bw3h);
    cudaGetSymbolAddress((void**)&perm1, g_perm1);
    cudaGetSymbolAddress((void**)&perm2, g_perm2);
    cudaGetSymbolAddress((void**)&cnt1, g_cnt1);
    cudaGetSymbolAddress((void**)&cnt2, g_cnt2);
    cudaGetSymbolAddress((void**)&st1, g_st1);
    cudaGetSymbolAddress((void**)&st2, g_st2);
    cudaGetSymbolAddress((void**)&cu1, g_cur1);
    cudaGetSymbolAddress((void**)&cu2, g_cur2);

    const int tiles1 = (N1 + TM - 1) / TM + 8;
    const int tiles2 = (N2 + TM - 1) / TM + 8;
    const int n1p = tiles1 * TM;
    const int n2p = tiles2 * TM;
    const int tiles3 = (N3 + TM - 1) / TM;
    const int t3a = (tiles3 + 1) / 2, t3b = tiles3 - t3a;

    // launches 1-3: prep chain
    k_prep<<<512, 256>>>(perm1, n1p, perm2, n2p, cnt1, cnt2, W3, Bw3h);
    k_hist2<<<512, 256>>>(offset1, N1, offset2, N2, cnt1, cnt2);
    k_scan2<<<1, 32>>>(cnt1, st1, cu1, cnt2, st2, cu2);
    // launches 4,5: y3 = feats3 @ W3 -> fp16 (dense, split so ncu -s captures a GEMM)
    k_gemm<256, C3, 1, true, false, true><<<t3a, 256, 32768>>>(feats3, nullptr, Bw3h,
        nullptr, nullptr, nullptr, N3, 0, y3h);
    k_gemm<256, C3, 1, true, false, true><<<t3b, 256, 32768>>>(feats3, nullptr, Bw3h,
        nullptr, nullptr, nullptr, N3, t3a, y3h);
    // launches 6,7: scatter + B builds
    k_scat2<<<(N1 + N2 + 255) / 256, 256>>>(offset1, N1, offset2, N2, cu1, cu2, perm1, perm2);
    k_build<<<(8 * 256 * 128 + 8 * 192 * 128 + 255) / 256, 256>>>(T2, W1, T3, W2, B2h, B3h);
    // launch 8: y2 = gather_tconv(y3, T3) + feats2 @ W2 -> fp16
    k_gemm<256, C2, C2, false, true, true><<<tiles2, 256, 32768>>>(y3h, feats2, B3h,
        perm2, parent2, st2, 0, 0, y2h);
    // launch 9: out = gather_tconv(y2, T2) + feats1 @ W1 -> fp32
    k_gemm<192, C2, C1, false, true, false><<<tiles1, 256, 32768>>>(y2h, feats1, B2h,
        perm1, parent1, st1, 0, 0, d_out);
}